// round 10
// baseline (speedup 1.0000x reference)
#include <cuda_runtime.h>

typedef unsigned long long u64;
typedef unsigned int u32;

#define BATCH 16
#define IMG_H 512
#define IMG_W 512
#define NPIX (IMG_H * IMG_W)          // 262144
#define TOTAL (BATCH * NPIX)          // 4194304
#define WPR 8                         // 64-bit words per row
#define ROWS (BATCH * IMG_H)          // 8192
#define NW (TOTAL / 64)               // 65536
#define WPI (NPIX / 64)               // 4096

#define GRID 128
#define BLOCK 256
#define NT (GRID * BLOCK)             // 32768 threads
#define NWARPS (NT / 32)

// Scratch (allocation-free)
__device__ u64 g_m0[NW];
__device__ u64 g_m1[NW];
__device__ u64 g_m2[NW];
__device__ int g_parent[TOTAL];
__device__ int g_csize[TOTAL];
__device__ int g_carry[NW];
__device__ int g_ncomp[BATCH];
__device__ unsigned g_bar_count = 0;
__device__ unsigned g_bar_gen = 0;    // monotonic across replays; only change-detection used

// ---------------------------------------------------------------------------
// Software grid barrier (all GRID blocks resident: GRID <= #SMs, 1 block/SM)
// ---------------------------------------------------------------------------
__device__ __forceinline__ void gbar() {
    __syncthreads();
    if (threadIdx.x == 0) {
        __threadfence();
        unsigned gen = *((volatile unsigned*)&g_bar_gen);
        unsigned t = atomicAdd(&g_bar_count, 1u);
        if (t == GRID - 1) {
            g_bar_count = 0;          // safe: nobody reads count except via atomicAdd of NEXT barrier
            __threadfence();
            atomicAdd(&g_bar_gen, 1u);
        } else {
            while (*((volatile unsigned*)&g_bar_gen) == gen) { __nanosleep(32); }
            __threadfence();
        }
    }
    __syncthreads();
}

// ---------------------------------------------------------------------------
// Structuring-element half-widths (compile-time)
// ---------------------------------------------------------------------------
template <int R>
__device__ __forceinline__ constexpr int hw_disk(int dy) {
    int best = 0;
    for (int x = 0; x <= R; x++)
        if (x * x + dy * dy <= R * R) best = x;
    return best;
}

// disk(2) (+) disk(5) Minkowski sum: hw(dy) = max_{a+b=dy} hw5(a)+hw2(b)
__device__ __forceinline__ constexpr int hw_comb(int dy) {
    int best = -1;
    for (int a = -5; a <= 5; a++) {
        int b = dy - a;
        if (b < -2 || b > 2) continue;
        int h5 = 0, h2 = 0;
        for (int x = 0; x <= 5; x++) if (x * x + a * a <= 25) h5 = x;
        for (int x = 0; x <= 2; x++) if (x * x + b * b <= 4)  h2 = x;
        if (h5 + h2 > best) best = h5 + h2;
    }
    return best;                       // -1 (row absent) never happens for |dy|<=7
}

// center-out row order for fast early exit
__device__ __forceinline__ constexpr int row_order(int i) {
    // 0, -1, 1, -2, 2, ...
    return (i & 1) ? -((i + 1) / 2) : (i / 2);
}

// ---------------------------------------------------------------------------
// Stages
// ---------------------------------------------------------------------------
__device__ void st_binarize(const float* __restrict__ in, u64* __restrict__ dst) {
    int tid = blockIdx.x * BLOCK + threadIdx.x;
    for (int g = tid; g < TOTAL; g += NT) {
        unsigned b = __ballot_sync(0xffffffffu, in[g] > 0.0f);
        if ((threadIdx.x & 31) == 0) ((u32*)dst)[g >> 5] = b;
    }
}

template <int R, bool COMB>
__device__ void st_erode(const u64* __restrict__ in, u64* __restrict__ dst) {
    int tid = blockIdx.x * BLOCK + threadIdx.x;
    const int NR = 2 * R + 1;
    for (int wg = tid; wg < NW; wg += NT) {
        int w = wg & (WPR - 1);
        int y = (wg / WPR) & (IMG_H - 1);
        u64 acc = ~0ull;
#pragma unroll
        for (int i = 0; i < NR; i++) {
            const int dy = row_order(i);
            int yy = y + dy;
            if (yy < 0 || yy >= IMG_H) continue;     // OOB row counts as 1
            int rw = wg + dy * WPR;
            u64 mid = in[rw];
            u64 lo = (w == 0) ? ~0ull : in[rw - 1];
            u64 hi = (w == WPR - 1) ? ~0ull : in[rw + 1];
            u64 a = mid;
            const int h = COMB ? hw_comb(dy) : hw_disk<R>(dy);
#pragma unroll
            for (int k = 1; k <= h; k++) {
                a &= (mid >> k) | (hi << (64 - k));
                a &= (mid << k) | (lo >> (64 - k));
            }
            acc &= a;
            if (!acc) break;
        }
        dst[wg] = acc;
    }
}

template <int R>
__device__ void st_dilate(const u64* __restrict__ in, u64* __restrict__ dst) {
    int tid = blockIdx.x * BLOCK + threadIdx.x;
    const int NR = 2 * R + 1;
    for (int wg = tid; wg < NW; wg += NT) {
        int w = wg & (WPR - 1);
        int y = (wg / WPR) & (IMG_H - 1);
        u64 acc = 0ull;
#pragma unroll
        for (int i = 0; i < NR; i++) {
            const int dy = row_order(i);
            int yy = y + dy;
            if (yy < 0 || yy >= IMG_H) continue;     // OOB row counts as 0
            int rw = wg + dy * WPR;
            u64 mid = in[rw];
            u64 lo = (w == 0) ? 0ull : in[rw - 1];
            u64 hi = (w == WPR - 1) ? 0ull : in[rw + 1];
            u64 a = mid;
            const int h = hw_disk<R>(dy);
#pragma unroll
            for (int k = 1; k <= h; k++) {
                a |= (mid >> k) | (hi << (64 - k));
                a |= (mid << k) | (lo >> (64 - k));
            }
            acc |= a;
            if (acc == ~0ull) break;
        }
        dst[wg] = acc;
    }
}

// dilate disk(1) fused with float unpack (warp per word, coalesced stores)
__device__ void st_dilate1_out(const u64* __restrict__ in, float* __restrict__ out) {
    int warp = (blockIdx.x * BLOCK + threadIdx.x) >> 5;
    int lane = threadIdx.x & 31;
    for (int wg = warp; wg < NW; wg += NWARPS) {
        int w = wg & (WPR - 1);
        int y = (wg / WPR) & (IMG_H - 1);
        u64 mid = in[wg];
        u64 lo = (w == 0) ? 0ull : in[wg - 1];
        u64 hi = (w == WPR - 1) ? 0ull : in[wg + 1];
        u64 a = mid | ((mid >> 1) | (hi << 63)) | ((mid << 1) | (lo >> 63));
        if (y > 0)          a |= in[wg - WPR];
        if (y < IMG_H - 1)  a |= in[wg + WPR];
        long long base = (long long)wg * 64;
        out[base + lane]      = ((a >> lane) & 1ull) ? 1.0f : 0.0f;
        out[base + 32 + lane] = ((a >> (lane + 32)) & 1ull) ? 1.0f : 0.0f;
    }
}

// ---------------------------------------------------------------------------
// Run-based CCL (4-connectivity)
// ---------------------------------------------------------------------------
__device__ __forceinline__ int uf_find(int i) {
    int p = g_parent[i];
    while (p != i) { i = p; p = g_parent[i]; }
    return i;
}

__device__ void uf_merge(int a, int b) {
    while (true) {
        a = uf_find(a);
        b = uf_find(b);
        if (a == b) return;
        int lo = a < b ? a : b;
        int hi = a < b ? b : a;
        int old = atomicMin(&g_parent[hi], lo);
        if (old == hi) return;
        a = lo; b = old;
    }
}

__device__ __forceinline__ int rs_of(u64 m, int j, int carry, int wordbase) {
    u64 zmask = (~m) & ((j == 0) ? 0ull : ((1ull << j) - 1ull));
    if (zmask) return wordbase + (63 - __clzll(zmask)) + 1;
    return carry;
}

__device__ void st_prep(const u64* __restrict__ in) {
    int tid = blockIdx.x * BLOCK + threadIdx.x;
    for (int r = tid; r < ROWS; r += NT) {
        if ((r & (IMG_H - 1)) == 0) g_ncomp[r >> 9] = 0;
        int rowbase = r * IMG_W;
        int carry = rowbase;
        u64 prevtop = 0;
#pragma unroll
        for (int w = 0; w < WPR; w++) {
            u64 m = in[r * WPR + w];
            g_carry[r * WPR + w] = carry;
            u64 starts = m & ~((m << 1) | prevtop);
            int wb = rowbase + 64 * w;
            while (starts) {
                int j = __ffsll((long long)starts) - 1;
                starts &= starts - 1;
                int idx = wb + j;
                g_parent[idx] = idx;
                g_csize[idx] = 0;
            }
            u64 nz = ~m;
            if (nz) carry = wb + (63 - __clzll(nz)) + 1;
            prevtop = m >> 63;
        }
    }
}

__device__ void st_merge(const u64* __restrict__ in) {
    int tid = blockIdx.x * BLOCK + threadIdx.x;
    for (int wg = tid; wg < NW; wg += NT) {
        int row = wg / WPR;
        if ((row & (IMG_H - 1)) == 0) continue;
        u64 cur = in[wg], up = in[wg - WPR];
        u64 both = cur & up;
        if (!both) continue;
        int cc = g_carry[wg], cu = g_carry[wg - WPR];
        int wb_c = wg * 64, wb_u = wb_c - IMG_W;
        while (both) {
            int j = __ffsll((long long)both) - 1;
            u64 run = both >> j;
            u64 inv = ~run;
            int len = inv ? (__ffsll((long long)inv) - 1) : (64 - j);
            uf_merge(rs_of(cur, j, cc, wb_c), rs_of(up, j, cu, wb_u));
            if (j + len >= 64) both = 0;
            else both &= ~(((1ull << len) - 1ull) << j);
        }
    }
}

__device__ void st_finalize(const u64* __restrict__ in) {
    int tid = blockIdx.x * BLOCK + threadIdx.x;
    for (int wg = tid; wg < NW; wg += NT) {
        u64 m = in[wg];
        if (!m) continue;
        int carry = g_carry[wg];
        int wb = wg * 64;
        int img = wg / WPI;
        u64 rem = m;
        while (rem) {
            int j = __ffsll((long long)rem) - 1;
            u64 run = rem >> j;
            u64 inv = ~run;
            int len = inv ? (__ffsll((long long)inv) - 1) : (64 - j);
            int rs = rs_of(m, j, carry, wb);
            int root = uf_find(rs);
            g_parent[rs] = root;                 // path compression
            atomicAdd(&g_csize[root], len);
            if (root == rs && rs == wb + j)
                atomicAdd(&g_ncomp[img], 1);
            if (j + len >= 64) rem = 0;
            else rem &= ~(((1ull << len) - 1ull) << j);
        }
    }
}

// remove_small_objects; optionally write inverted mask (for hole-filling path)
__device__ void st_filter_obj(const u64* __restrict__ in, u64* __restrict__ dst,
                              int min_size, bool guard, bool inv_out) {
    int tid = blockIdx.x * BLOCK + threadIdx.x;
    for (int wg = tid; wg < NW; wg += NT) {
        u64 m = in[wg];
        u64 out = 0;
        if (m) {
            int carry = g_carry[wg];
            int wb = wg * 64;
            bool keepall = guard && (g_ncomp[wg / WPI] <= 1);
            u64 rem = m;
            while (rem) {
                int j = __ffsll((long long)rem) - 1;
                u64 run = rem >> j;
                u64 inv = ~run;
                int len = inv ? (__ffsll((long long)inv) - 1) : (64 - j);
                u64 segbits = (j + len >= 64) ? (~0ull << j)
                                              : (((1ull << len) - 1ull) << j);
                int rs = rs_of(m, j, carry, wb);
                int sz = g_csize[g_parent[rs]];
                if (keepall || sz >= min_size) out |= segbits;
                rem &= ~segbits;
            }
        }
        dst[wg] = inv_out ? ~out : out;
    }
}

// hole filling: in = bg mask (CCL done). fg = ~bg | (bg comp < min_size)
__device__ void st_filter_holes(const u64* __restrict__ in, u64* __restrict__ dst,
                                int min_size) {
    int tid = blockIdx.x * BLOCK + threadIdx.x;
    for (int wg = tid; wg < NW; wg += NT) {
        u64 m = in[wg];
        u64 out = ~m;
        if (m) {
            int carry = g_carry[wg];
            int wb = wg * 64;
            u64 rem = m;
            while (rem) {
                int j = __ffsll((long long)rem) - 1;
                u64 run = rem >> j;
                u64 inv = ~run;
                int len = inv ? (__ffsll((long long)inv) - 1) : (64 - j);
                u64 segbits = (j + len >= 64) ? (~0ull << j)
                                              : (((1ull << len) - 1ull) << j);
                int rs = rs_of(m, j, carry, wb);
                if (g_csize[g_parent[rs]] < min_size) out |= segbits;
                rem &= ~segbits;
            }
        }
        dst[wg] = out;
    }
}

// ---------------------------------------------------------------------------
// One persistent kernel for the whole pipeline
// ---------------------------------------------------------------------------
__global__ void __launch_bounds__(BLOCK, 1)
k_pipeline(const float* __restrict__ in, float* __restrict__ out) {
    // fg0 -> m0
    st_binarize(in, g_m0);                          gbar();

    // remove_small_objects(m0, 2000, guard); write bg = ~kept -> m1
    st_prep(g_m0);                                  gbar();
    st_merge(g_m0);                                 gbar();
    st_finalize(g_m0);                              gbar();
    st_filter_obj(g_m0, g_m1, 2000, true, true);    gbar();

    // fill holes: CCL on bg (m1); fg -> m0
    st_prep(g_m1);                                  gbar();
    st_merge(g_m1);                                 gbar();
    st_finalize(g_m1);                              gbar();
    st_filter_holes(g_m1, g_m0, 301);               gbar();

    // erosion disk2 then opening-erode disk5, fused: erode by disk2 (+) disk5
    st_erode<7, true>(g_m0, g_m1);                  gbar();
    // opening-dilate disk5
    st_dilate<5>(g_m1, g_m2);                       gbar();

    // remove_small_objects(m2, 2000, guard) -> m0
    st_prep(g_m2);                                  gbar();
    st_merge(g_m2);                                 gbar();
    st_finalize(g_m2);                              gbar();
    st_filter_obj(g_m2, g_m0, 2000, true, false);   gbar();

    // dilation disk1 + float unpack
    st_dilate1_out(g_m0, out);
}

extern "C" void kernel_launch(void* const* d_in, const int* in_sizes, int n_in,
                              void* d_out, int out_size) {
    const float* in = (const float*)d_in[0];
    float* out = (float*)d_out;
    k_pipeline<<<GRID, BLOCK>>>(in, out);
}

// round 11
// speedup vs baseline: 1.3642x; 1.3642x over previous
#include <cuda_runtime.h>

typedef unsigned long long u64;
typedef unsigned int u32;

#define BATCH 16
#define IMG_H 512
#define IMG_W 512
#define NPIX (IMG_H * IMG_W)          // 262144
#define TOTAL (BATCH * NPIX)          // 4194304
#define WPR 8                         // 64-bit words per row
#define ROWS (BATCH * IMG_H)          // 8192
#define NW (TOTAL / 64)               // 65536
#define WPI (NPIX / 64)               // 4096

#define GRID 296                      // 2 CTAs per SM (148 SMs), all wave-1 resident
#define BLOCK 1024
#define NT (GRID * BLOCK)             // 303104 threads
#define NWARPS (NT / 32)

// Scratch (allocation-free)
__device__ u64 g_m0[NW];
__device__ u64 g_m1[NW];
__device__ u64 g_m2[NW];
__device__ int g_parent[TOTAL];
__device__ int g_csize[TOTAL];
__device__ int g_carry[NW];
__device__ int g_ncomp[BATCH];
__device__ unsigned g_bar_count = 0;
__device__ unsigned g_bar_gen = 0;    // monotonic across replays; change-detection only

// ---------------------------------------------------------------------------
// Software grid barrier. GRID CTAs are guaranteed co-resident:
// 1024 thr × 2 blocks = 2048 thr/SM (max), <=32 regs via launch_bounds.
// ---------------------------------------------------------------------------
__device__ __forceinline__ void gbar() {
    __syncthreads();
    if (threadIdx.x == 0) {
        __threadfence();
        unsigned gen = *((volatile unsigned*)&g_bar_gen);
        unsigned t = atomicAdd(&g_bar_count, 1u);
        if (t == GRID - 1) {
            g_bar_count = 0;          // safe: count re-read only via next barrier's atomicAdd
            __threadfence();
            atomicAdd(&g_bar_gen, 1u);
        } else {
            while (*((volatile unsigned*)&g_bar_gen) == gen) { __nanosleep(32); }
            __threadfence();
        }
    }
    __syncthreads();
}

// ---------------------------------------------------------------------------
// Structuring-element half-widths (compile-time)
// ---------------------------------------------------------------------------
template <int R>
__device__ __forceinline__ constexpr int hw_disk(int dy) {
    int best = 0;
    for (int x = 0; x <= R; x++)
        if (x * x + dy * dy <= R * R) best = x;
    return best;
}

// disk(2) (+) disk(5) Minkowski sum: hw(dy) = max_{a+b=dy} hw5(a)+hw2(b)
__device__ __forceinline__ constexpr int hw_comb(int dy) {
    int best = -1;
    for (int a = -5; a <= 5; a++) {
        int b = dy - a;
        if (b < -2 || b > 2) continue;
        int h5 = 0, h2 = 0;
        for (int x = 0; x <= 5; x++) if (x * x + a * a <= 25) h5 = x;
        for (int x = 0; x <= 2; x++) if (x * x + b * b <= 4)  h2 = x;
        if (h5 + h2 > best) best = h5 + h2;
    }
    return best;
}

// center-out row order for fast early exit: 0, -1, 1, -2, 2, ...
__device__ __forceinline__ constexpr int row_order(int i) {
    return (i & 1) ? -((i + 1) / 2) : (i / 2);
}

// ---------------------------------------------------------------------------
// Stages
// ---------------------------------------------------------------------------
__device__ void st_binarize(const float* __restrict__ in, u64* __restrict__ dst) {
    int tid = blockIdx.x * BLOCK + threadIdx.x;
    for (int g = tid; g < TOTAL; g += NT) {
        unsigned b = __ballot_sync(0xffffffffu, in[g] > 0.0f);
        if ((threadIdx.x & 31) == 0) ((u32*)dst)[g >> 5] = b;
    }
}

template <int R, bool COMB>
__device__ void st_erode(const u64* __restrict__ in, u64* __restrict__ dst) {
    int tid = blockIdx.x * BLOCK + threadIdx.x;
    const int NR = 2 * R + 1;
    for (int wg = tid; wg < NW; wg += NT) {
        int w = wg & (WPR - 1);
        int y = (wg / WPR) & (IMG_H - 1);
        u64 acc = ~0ull;
#pragma unroll
        for (int i = 0; i < NR; i++) {
            const int dy = row_order(i);
            int yy = y + dy;
            if (yy < 0 || yy >= IMG_H) continue;     // OOB row counts as 1
            int rw = wg + dy * WPR;
            u64 mid = in[rw];
            u64 lo = (w == 0) ? ~0ull : in[rw - 1];
            u64 hi = (w == WPR - 1) ? ~0ull : in[rw + 1];
            u64 a = mid;
            const int h = COMB ? hw_comb(dy) : hw_disk<R>(dy);
#pragma unroll
            for (int k = 1; k <= h; k++) {
                a &= (mid >> k) | (hi << (64 - k));
                a &= (mid << k) | (lo >> (64 - k));
            }
            acc &= a;
            if (!acc) break;
        }
        dst[wg] = acc;
    }
}

template <int R>
__device__ void st_dilate(const u64* __restrict__ in, u64* __restrict__ dst) {
    int tid = blockIdx.x * BLOCK + threadIdx.x;
    const int NR = 2 * R + 1;
    for (int wg = tid; wg < NW; wg += NT) {
        int w = wg & (WPR - 1);
        int y = (wg / WPR) & (IMG_H - 1);
        u64 acc = 0ull;
#pragma unroll
        for (int i = 0; i < NR; i++) {
            const int dy = row_order(i);
            int yy = y + dy;
            if (yy < 0 || yy >= IMG_H) continue;     // OOB row counts as 0
            int rw = wg + dy * WPR;
            u64 mid = in[rw];
            u64 lo = (w == 0) ? 0ull : in[rw - 1];
            u64 hi = (w == WPR - 1) ? 0ull : in[rw + 1];
            u64 a = mid;
            const int h = hw_disk<R>(dy);
#pragma unroll
            for (int k = 1; k <= h; k++) {
                a |= (mid >> k) | (hi << (64 - k));
                a |= (mid << k) | (lo >> (64 - k));
            }
            acc |= a;
            if (acc == ~0ull) break;
        }
        dst[wg] = acc;
    }
}

// dilate disk(1) fused with float unpack (warp per word, coalesced stores)
__device__ void st_dilate1_out(const u64* __restrict__ in, float* __restrict__ out) {
    int warp = (blockIdx.x * BLOCK + threadIdx.x) >> 5;
    int lane = threadIdx.x & 31;
    for (int wg = warp; wg < NW; wg += NWARPS) {
        int w = wg & (WPR - 1);
        int y = (wg / WPR) & (IMG_H - 1);
        u64 mid = in[wg];
        u64 lo = (w == 0) ? 0ull : in[wg - 1];
        u64 hi = (w == WPR - 1) ? 0ull : in[wg + 1];
        u64 a = mid | ((mid >> 1) | (hi << 63)) | ((mid << 1) | (lo >> 63));
        if (y > 0)          a |= in[wg - WPR];
        if (y < IMG_H - 1)  a |= in[wg + WPR];
        long long base = (long long)wg * 64;
        out[base + lane]      = ((a >> lane) & 1ull) ? 1.0f : 0.0f;
        out[base + 32 + lane] = ((a >> (lane + 32)) & 1ull) ? 1.0f : 0.0f;
    }
}

// ---------------------------------------------------------------------------
// Run-based CCL (4-connectivity)
// ---------------------------------------------------------------------------
__device__ __forceinline__ int uf_find(int i) {
    int p = g_parent[i];
    while (p != i) { i = p; p = g_parent[i]; }
    return i;
}

__device__ void uf_merge(int a, int b) {
    while (true) {
        a = uf_find(a);
        b = uf_find(b);
        if (a == b) return;
        int lo = a < b ? a : b;
        int hi = a < b ? b : a;
        int old = atomicMin(&g_parent[hi], lo);
        if (old == hi) return;
        a = lo; b = old;
    }
}

__device__ __forceinline__ int rs_of(u64 m, int j, int carry, int wordbase) {
    u64 zmask = (~m) & ((j == 0) ? 0ull : ((1ull << j) - 1ull));
    if (zmask) return wordbase + (63 - __clzll(zmask)) + 1;
    return carry;
}

__device__ void st_prep(const u64* __restrict__ in) {
    int tid = blockIdx.x * BLOCK + threadIdx.x;
    for (int r = tid; r < ROWS; r += NT) {
        if ((r & (IMG_H - 1)) == 0) g_ncomp[r >> 9] = 0;
        int rowbase = r * IMG_W;
        int carry = rowbase;
        u64 prevtop = 0;
#pragma unroll
        for (int w = 0; w < WPR; w++) {
            u64 m = in[r * WPR + w];
            g_carry[r * WPR + w] = carry;
            u64 starts = m & ~((m << 1) | prevtop);
            int wb = rowbase + 64 * w;
            while (starts) {
                int j = __ffsll((long long)starts) - 1;
                starts &= starts - 1;
                int idx = wb + j;
                g_parent[idx] = idx;
                g_csize[idx] = 0;
            }
            u64 nz = ~m;
            if (nz) carry = wb + (63 - __clzll(nz)) + 1;
            prevtop = m >> 63;
        }
    }
}

__device__ void st_merge(const u64* __restrict__ in) {
    int tid = blockIdx.x * BLOCK + threadIdx.x;
    for (int wg = tid; wg < NW; wg += NT) {
        int row = wg / WPR;
        if ((row & (IMG_H - 1)) == 0) continue;
        u64 cur = in[wg], up = in[wg - WPR];
        u64 both = cur & up;
        if (!both) continue;
        int cc = g_carry[wg], cu = g_carry[wg - WPR];
        int wb_c = wg * 64, wb_u = wb_c - IMG_W;
        while (both) {
            int j = __ffsll((long long)both) - 1;
            u64 run = both >> j;
            u64 inv = ~run;
            int len = inv ? (__ffsll((long long)inv) - 1) : (64 - j);
            uf_merge(rs_of(cur, j, cc, wb_c), rs_of(up, j, cu, wb_u));
            if (j + len >= 64) both = 0;
            else both &= ~(((1ull << len) - 1ull) << j);
        }
    }
}

__device__ void st_finalize(const u64* __restrict__ in) {
    int tid = blockIdx.x * BLOCK + threadIdx.x;
    for (int wg = tid; wg < NW; wg += NT) {
        u64 m = in[wg];
        if (!m) continue;
        int carry = g_carry[wg];
        int wb = wg * 64;
        int img = wg / WPI;
        u64 rem = m;
        while (rem) {
            int j = __ffsll((long long)rem) - 1;
            u64 run = rem >> j;
            u64 inv = ~run;
            int len = inv ? (__ffsll((long long)inv) - 1) : (64 - j);
            int rs = rs_of(m, j, carry, wb);
            int root = uf_find(rs);
            g_parent[rs] = root;                 // path compression
            atomicAdd(&g_csize[root], len);
            if (root == rs && rs == wb + j)
                atomicAdd(&g_ncomp[img], 1);
            if (j + len >= 64) rem = 0;
            else rem &= ~(((1ull << len) - 1ull) << j);
        }
    }
}

// remove_small_objects; optionally write inverted mask (for hole-filling path)
__device__ void st_filter_obj(const u64* __restrict__ in, u64* __restrict__ dst,
                              int min_size, bool guard, bool inv_out) {
    int tid = blockIdx.x * BLOCK + threadIdx.x;
    for (int wg = tid; wg < NW; wg += NT) {
        u64 m = in[wg];
        u64 out = 0;
        if (m) {
            int carry = g_carry[wg];
            int wb = wg * 64;
            bool keepall = guard && (g_ncomp[wg / WPI] <= 1);
            u64 rem = m;
            while (rem) {
                int j = __ffsll((long long)rem) - 1;
                u64 run = rem >> j;
                u64 inv = ~run;
                int len = inv ? (__ffsll((long long)inv) - 1) : (64 - j);
                u64 segbits = (j + len >= 64) ? (~0ull << j)
                                              : (((1ull << len) - 1ull) << j);
                int rs = rs_of(m, j, carry, wb);
                int sz = g_csize[g_parent[rs]];
                if (keepall || sz >= min_size) out |= segbits;
                rem &= ~segbits;
            }
        }
        dst[wg] = inv_out ? ~out : out;
    }
}

// hole filling: in = bg mask (CCL done). fg = ~bg | (bg comp < min_size)
__device__ void st_filter_holes(const u64* __restrict__ in, u64* __restrict__ dst,
                                int min_size) {
    int tid = blockIdx.x * BLOCK + threadIdx.x;
    for (int wg = tid; wg < NW; wg += NT) {
        u64 m = in[wg];
        u64 out = ~m;
        if (m) {
            int carry = g_carry[wg];
            int wb = wg * 64;
            u64 rem = m;
            while (rem) {
                int j = __ffsll((long long)rem) - 1;
                u64 run = rem >> j;
                u64 inv = ~run;
                int len = inv ? (__ffsll((long long)inv) - 1) : (64 - j);
                u64 segbits = (j + len >= 64) ? (~0ull << j)
                                              : (((1ull << len) - 1ull) << j);
                int rs = rs_of(m, j, carry, wb);
                if (g_csize[g_parent[rs]] < min_size) out |= segbits;
                rem &= ~segbits;
            }
        }
        dst[wg] = out;
    }
}

// ---------------------------------------------------------------------------
// One persistent kernel, full occupancy
// ---------------------------------------------------------------------------
__global__ void __launch_bounds__(BLOCK, 2)
k_pipeline(const float* __restrict__ in, float* __restrict__ out) {
    // fg0 -> m0
    st_binarize(in, g_m0);                          gbar();

    // remove_small_objects(m0, 2000, guard); write bg = ~kept -> m1
    st_prep(g_m0);                                  gbar();
    st_merge(g_m0);                                 gbar();
    st_finalize(g_m0);                              gbar();
    st_filter_obj(g_m0, g_m1, 2000, true, true);    gbar();

    // fill holes: CCL on bg (m1); fg -> m0
    st_prep(g_m1);                                  gbar();
    st_merge(g_m1);                                 gbar();
    st_finalize(g_m1);                              gbar();
    st_filter_holes(g_m1, g_m0, 301);               gbar();

    // erosion disk2 then opening-erode disk5, fused: erode by disk2 (+) disk5
    st_erode<7, true>(g_m0, g_m1);                  gbar();
    // opening-dilate disk5
    st_dilate<5>(g_m1, g_m2);                       gbar();

    // remove_small_objects(m2, 2000, guard) -> m0
    st_prep(g_m2);                                  gbar();
    st_merge(g_m2);                                 gbar();
    st_finalize(g_m2);                              gbar();
    st_filter_obj(g_m2, g_m0, 2000, true, false);   gbar();

    // dilation disk1 + float unpack
    st_dilate1_out(g_m0, out);
}

extern "C" void kernel_launch(void* const* d_in, const int* in_sizes, int n_in,
                              void* d_out, int out_size) {
    const float* in = (const float*)d_in[0];
    float* out = (float*)d_out;
    k_pipeline<<<GRID, BLOCK>>>(in, out);
}